// round 1
// baseline (speedup 1.0000x reference)
#include <cuda_runtime.h>
#include <math.h>

#define NE 8      // experts
#define ND 16     // robot_state_size
#define NF 16     // freq bands
#define NH 512    // hidden
#define NG 16     // gate input
#define NB 8192   // batch
#define TWO_PI 6.283185307179586f

// ---------------- device scratch (no dynamic alloc allowed) ----------------
__device__ int   g_count[NE];
__device__ int   g_rows[NE * NB];
__device__ float g_gate[NE * NB];
__device__ __align__(16) float g_mid[(size_t)NE * NB * NH];   // 128 MB

__device__ __forceinline__ float gelu_exact(float x) {
    return 0.5f * x * (1.0f + erff(x * 0.70710678118654752f));
}

// ---------------- init: zero output buffer + expert counters ----------------
__global__ void k_init(float* __restrict__ out, int out_size) {
    int idx = blockIdx.x * blockDim.x + threadIdx.x;
    if (idx < NE) g_count[idx] = 0;
    for (int i = idx; i < out_size; i += gridDim.x * blockDim.x)
        out[i] = 0.0f;
}

// ---------------- gate: logits -> softmax -> top2 -> renorm -> scatter ------
__global__ void k_gate(const float* __restrict__ gin, const int* __restrict__ task_p,
                       const float* __restrict__ gw, const float* __restrict__ gb) {
    __shared__ float sw[NG * NE];
    __shared__ float sb[NE];
    int task = task_p[0];
    for (int i = threadIdx.x; i < NG * NE; i += blockDim.x)
        sw[i] = gw[task * NG * NE + i];
    if (threadIdx.x < NE) sb[threadIdx.x] = gb[task * NE + threadIdx.x];
    __syncthreads();

    int b = blockIdx.x * blockDim.x + threadIdx.x;
    if (b >= NB) return;

    float x[NG];
#pragma unroll
    for (int g = 0; g < NG; g++) x[g] = gin[b * NG + g];

    float lg[NE];
#pragma unroll
    for (int e = 0; e < NE; e++) {
        float s = sb[e];
#pragma unroll
        for (int g = 0; g < NG; g++) s += x[g] * sw[g * NE + e];
        lg[e] = s;
    }
    float m = lg[0];
#pragma unroll
    for (int e = 1; e < NE; e++) m = fmaxf(m, lg[e]);
    float p[NE];
#pragma unroll
    for (int e = 0; e < NE; e++) p[e] = expf(lg[e] - m);

    // top-2 (ties -> lower index, matching lax.top_k)
    int i0 = 0; float v0 = p[0];
#pragma unroll
    for (int e = 1; e < NE; e++) if (p[e] > v0) { v0 = p[e]; i0 = e; }
    int i1 = (i0 == 0) ? 1 : 0; float v1 = p[i1];
#pragma unroll
    for (int e = 0; e < NE; e++) if (e != i0 && p[e] > v1) { v1 = p[e]; i1 = e; }

    float inv = 1.0f / (v0 + v1);   // softmax denom cancels in the ratio
    v0 *= inv; v1 *= inv;

    int p0 = atomicAdd(&g_count[i0], 1);
    g_rows[i0 * NB + p0] = b; g_gate[i0 * NB + p0] = v0;
    int p1 = atomicAdd(&g_count[i1], 1);
    g_rows[i1 * NB + p1] = b; g_gate[i1 * NB + p1] = v1;
}

// ---------------- stage 1: fourier feat -> per-dim linear -> LN -> gelu -> sum_d
// One warp per (expert,slot). 8 warps/block share W1[e][d] via smem staging.
__global__ __launch_bounds__(256) void k_stage1(
    const float* __restrict__ xin,  const float* __restrict__ freqs,
    const float* __restrict__ w1,   const float* __restrict__ b1,
    const float* __restrict__ lng,  const float* __restrict__ lnb) {
    int e = blockIdx.y;
    int cnt = g_count[e];
    if ((int)blockIdx.x * 8 >= cnt) return;

    __shared__ float4 wb[16 * 128];          // 16 rows x 512 cols = 32 KB

    int tid = threadIdx.x;
    int warp = tid >> 5, lane = tid & 31;
    int slot = blockIdx.x * 8 + warp;
    bool act = slot < cnt;
    int row = g_rows[e * NB + (act ? slot : 0)];

    float xi_l = (lane < ND) ? xin[row * ND + lane] : 0.0f;

    float4 acc4[4];
#pragma unroll
    for (int q = 0; q < 4; q++) acc4[q] = make_float4(0.f, 0.f, 0.f, 0.f);

    const float* w1e = w1 + (size_t)e * ND * 33 * NH;

    for (int d = 0; d < ND; d++) {
        float xd = __shfl_sync(0xffffffffu, xi_l, d);
        int f = lane & 15;
        float ang = xd * freqs[(e * ND + d) * NF + f] * TWO_PI;
        float feat = (lane < 16) ? cosf(ang) : sinf(ang);

        const float* w1d = w1e + (size_t)d * 33 * NH;

        // h = b1
        float4 h4[4];
        const float4* b1d = (const float4*)(b1 + (size_t)(e * ND + d) * NH);
#pragma unroll
        for (int q = 0; q < 4; q++) h4[q] = b1d[lane + 32 * q];

        // ---- phase A: cos rows f=0..15 ----
        __syncthreads();
        {
            const float4* src = (const float4*)w1d;
#pragma unroll
            for (int i = 0; i < 8; i++) wb[tid + i * 256] = src[tid + i * 256];
        }
        __syncthreads();
#pragma unroll
        for (int f2 = 0; f2 < 16; f2++) {
            float fv = __shfl_sync(0xffffffffu, feat, f2);
#pragma unroll
            for (int q = 0; q < 4; q++) {
                float4 w = wb[f2 * 128 + lane + 32 * q];
                h4[q].x += fv * w.x; h4[q].y += fv * w.y;
                h4[q].z += fv * w.z; h4[q].w += fv * w.w;
            }
        }

        // ---- phase B: sin rows f=16..31 ----
        __syncthreads();
        {
            const float4* src = (const float4*)(w1d + 16 * NH);
#pragma unroll
            for (int i = 0; i < 8; i++) wb[tid + i * 256] = src[tid + i * 256];
        }
        __syncthreads();
#pragma unroll
        for (int f2 = 0; f2 < 16; f2++) {
            float fv = __shfl_sync(0xffffffffu, feat, 16 + f2);
#pragma unroll
            for (int q = 0; q < 4; q++) {
                float4 w = wb[f2 * 128 + lane + 32 * q];
                h4[q].x += fv * w.x; h4[q].y += fv * w.y;
                h4[q].z += fv * w.z; h4[q].w += fv * w.w;
            }
        }

        // ---- identity row f=32 (weight * xi), direct LDG (small, L1-cached) ----
        {
            const float4* w32 = (const float4*)(w1d + 32 * NH);
#pragma unroll
            for (int q = 0; q < 4; q++) {
                float4 w = __ldg(&w32[lane + 32 * q]);
                h4[q].x += xd * w.x; h4[q].y += xd * w.y;
                h4[q].z += xd * w.z; h4[q].w += xd * w.w;
            }
        }

        // ---- LayerNorm over H=512 (warp owns the whole row) ----
        float s = 0.f, s2 = 0.f;
#pragma unroll
        for (int q = 0; q < 4; q++) {
            s  += h4[q].x + h4[q].y + h4[q].z + h4[q].w;
            s2 += h4[q].x * h4[q].x + h4[q].y * h4[q].y
                + h4[q].z * h4[q].z + h4[q].w * h4[q].w;
        }
#pragma unroll
        for (int o = 16; o > 0; o >>= 1) {
            s  += __shfl_xor_sync(0xffffffffu, s,  o);
            s2 += __shfl_xor_sync(0xffffffffu, s2, o);
        }
        float mu = s * (1.0f / NH);
        float var = s2 * (1.0f / NH) - mu * mu;
        float rstd = rsqrtf(var + 1e-5f);

        const float4* gd = (const float4*)(lng + (size_t)(e * ND + d) * NH);
        const float4* bd = (const float4*)(lnb + (size_t)(e * ND + d) * NH);
#pragma unroll
        for (int q = 0; q < 4; q++) {
            float4 gv = __ldg(&gd[lane + 32 * q]);
            float4 bv = __ldg(&bd[lane + 32 * q]);
            float n0 = (h4[q].x - mu) * rstd * gv.x + bv.x;
            float n1 = (h4[q].y - mu) * rstd * gv.y + bv.y;
            float n2 = (h4[q].z - mu) * rstd * gv.z + bv.z;
            float n3 = (h4[q].w - mu) * rstd * gv.w + bv.w;
            acc4[q].x += gelu_exact(n0);
            acc4[q].y += gelu_exact(n1);
            acc4[q].z += gelu_exact(n2);
            acc4[q].w += gelu_exact(n3);
        }
    }

    if (act) {
        float4* dst = (float4*)(g_mid + (size_t)(e * NB + slot) * NH);
#pragma unroll
        for (int q = 0; q < 4; q++) dst[lane + 32 * q] = acc4[q];
    }
}

// ---------------- stage 2: per-expert GEMM mid[cnt,512] @ wo[512,512], scatter
__global__ __launch_bounds__(256) void k_stage2(
    const float* __restrict__ wo, const float* __restrict__ bo,
    float* __restrict__ out) {
    int e = blockIdx.z;
    int cnt = g_count[e];
    int rowbase = blockIdx.x * 64;
    if (rowbase >= cnt) return;
    int colbase = blockIdx.y * 64;

    __shared__ float  As[64][17];
    __shared__ float4 Bs[16][16];

    int tid = threadIdx.x;
    int tx = tid & 15, ty = tid >> 4;

    float4 racc[4];
#pragma unroll
    for (int i = 0; i < 4; i++) racc[i] = make_float4(0.f, 0.f, 0.f, 0.f);

    const float* mide = g_mid + (size_t)(e * NB + rowbase) * NH;
    const float* woe  = wo + (size_t)e * NH * NH + colbase;

    int ar = tid >> 2, akq = tid & 3;
    bool aval = (rowbase + ar) < cnt;
    int bk = tid >> 4;   // 0..15

    for (int k0 = 0; k0 < NH; k0 += 16) {
        float4 av = aval ? *(const float4*)(mide + (size_t)ar * NH + k0 + akq * 4)
                         : make_float4(0.f, 0.f, 0.f, 0.f);
        As[ar][akq * 4 + 0] = av.x;
        As[ar][akq * 4 + 1] = av.y;
        As[ar][akq * 4 + 2] = av.z;
        As[ar][akq * 4 + 3] = av.w;
        Bs[bk][tx] = *(const float4*)(woe + (size_t)(k0 + bk) * NH + tx * 4);
        __syncthreads();

#pragma unroll
        for (int kk = 0; kk < 16; kk++) {
            float4 bv = Bs[kk][tx];
            float a0 = As[ty * 4 + 0][kk];
            float a1 = As[ty * 4 + 1][kk];
            float a2 = As[ty * 4 + 2][kk];
            float a3 = As[ty * 4 + 3][kk];
            racc[0].x += a0 * bv.x; racc[0].y += a0 * bv.y; racc[0].z += a0 * bv.z; racc[0].w += a0 * bv.w;
            racc[1].x += a1 * bv.x; racc[1].y += a1 * bv.y; racc[1].z += a1 * bv.z; racc[1].w += a1 * bv.w;
            racc[2].x += a2 * bv.x; racc[2].y += a2 * bv.y; racc[2].z += a2 * bv.z; racc[2].w += a2 * bv.w;
            racc[3].x += a3 * bv.x; racc[3].y += a3 * bv.y; racc[3].z += a3 * bv.z; racc[3].w += a3 * bv.w;
        }
        __syncthreads();
    }

    float4 bov = *(const float4*)(bo + (size_t)e * NH + colbase + tx * 4);
#pragma unroll
    for (int i = 0; i < 4; i++) {
        int slot = rowbase + ty * 4 + i;
        if (slot < cnt) {
            int b = g_rows[e * NB + slot];
            float gwv = g_gate[e * NB + slot];
            float* o = out + (size_t)b * NH + colbase + tx * 4;
            atomicAdd(o + 0, gwv * (racc[i].x + bov.x));
            atomicAdd(o + 1, gwv * (racc[i].y + bov.y));
            atomicAdd(o + 2, gwv * (racc[i].z + bov.z));
            atomicAdd(o + 3, gwv * (racc[i].w + bov.w));
        }
    }
}

// ---------------- launch ----------------
extern "C" void kernel_launch(void* const* d_in, const int* in_sizes, int n_in,
                              void* d_out, int out_size) {
    const float* gate_input   = (const float*)d_in[0];
    const float* expert_input = (const float*)d_in[1];
    const int*   task_bh      = (const int*)  d_in[2];
    const float* gate_w       = (const float*)d_in[3];
    const float* gate_b       = (const float*)d_in[4];
    const float* freqs        = (const float*)d_in[5];
    const float* w1           = (const float*)d_in[6];
    const float* b1           = (const float*)d_in[7];
    const float* ln_g         = (const float*)d_in[8];
    const float* ln_b         = (const float*)d_in[9];
    const float* wo           = (const float*)d_in[10];
    const float* bo           = (const float*)d_in[11];
    float* out = (float*)d_out;

    k_init<<<2048, 256>>>(out, out_size);
    k_gate<<<NB / 256, 256>>>(gate_input, task_bh, gate_w, gate_b);
    k_stage1<<<dim3(NB / 8, NE), 256>>>(expert_input, freqs, w1, b1, ln_g, ln_b);
    k_stage2<<<dim3(NB / 64, NH / 64, NE), 256>>>(wo, bo, out);
}

// round 8
// speedup vs baseline: 1.1200x; 1.1200x over previous
#include <cuda_runtime.h>
#include <math.h>

#define NE 8      // experts
#define ND 16     // robot_state_size
#define NF 16     // freq bands
#define NH 512    // hidden
#define NG 16     // gate input
#define NB 8192   // batch
#define TWO_PI 6.283185307179586f

// ---------------- device scratch (no dynamic alloc allowed) ----------------
__device__ int   g_count[NE];
__device__ int   g_rows[NE * NB];
__device__ float g_gate[NE * NB];
__device__ __align__(16) float g_mid[(size_t)NE * NB * NH];   // 128 MB

__device__ __forceinline__ float gelu_exact(float x) {
    return 0.5f * x * (1.0f + erff(x * 0.70710678118654752f));
}

// ---------------- init: zero output buffer + expert counters ----------------
__global__ void k_init(float* __restrict__ out, int out_size) {
    int idx = blockIdx.x * blockDim.x + threadIdx.x;
    if (idx < NE) g_count[idx] = 0;
    for (int i = idx; i < out_size; i += gridDim.x * blockDim.x)
        out[i] = 0.0f;
}

// ---------------- gate: logits -> softmax -> top2 -> renorm -> scatter ------
__global__ void k_gate(const float* __restrict__ gin, const int* __restrict__ task_p,
                       const float* __restrict__ gw, const float* __restrict__ gb) {
    __shared__ float sw[NG * NE];
    __shared__ float sb[NE];
    int task = task_p[0];
    for (int i = threadIdx.x; i < NG * NE; i += blockDim.x)
        sw[i] = gw[task * NG * NE + i];
    if (threadIdx.x < NE) sb[threadIdx.x] = gb[task * NE + threadIdx.x];
    __syncthreads();

    int b = blockIdx.x * blockDim.x + threadIdx.x;
    if (b >= NB) return;

    float x[NG];
#pragma unroll
    for (int g = 0; g < NG; g++) x[g] = gin[b * NG + g];

    float lg[NE];
#pragma unroll
    for (int e = 0; e < NE; e++) {
        float s = sb[e];
#pragma unroll
        for (int g = 0; g < NG; g++) s += x[g] * sw[g * NE + e];
        lg[e] = s;
    }
    float m = lg[0];
#pragma unroll
    for (int e = 1; e < NE; e++) m = fmaxf(m, lg[e]);
    float p[NE];
#pragma unroll
    for (int e = 0; e < NE; e++) p[e] = expf(lg[e] - m);

    // top-2 (ties -> lower index, matching lax.top_k)
    int i0 = 0; float v0 = p[0];
#pragma unroll
    for (int e = 1; e < NE; e++) if (p[e] > v0) { v0 = p[e]; i0 = e; }
    int i1 = (i0 == 0) ? 1 : 0; float v1 = p[i1];
#pragma unroll
    for (int e = 0; e < NE; e++) if (e != i0 && p[e] > v1) { v1 = p[e]; i1 = e; }

    float inv = 1.0f / (v0 + v1);   // softmax denom cancels in the ratio
    v0 *= inv; v1 *= inv;

    int p0 = atomicAdd(&g_count[i0], 1);
    g_rows[i0 * NB + p0] = b; g_gate[i0 * NB + p0] = v0;
    int p1 = atomicAdd(&g_count[i1], 1);
    g_rows[i1 * NB + p1] = b; g_gate[i1 * NB + p1] = v1;
}

// ---------------- stage 1: fourier feat -> per-dim linear -> LN -> gelu -> sum_d
// Block: 32 slots x 512 cols of one expert. Thread: 8 slots x 8 cols.
// Weights streamed from L1 (__ldg), feat broadcast from smem -> FMA-bound.
// Outer d-loop kept rolled (unroll 1) to bound code size / compile time.
__global__ __launch_bounds__(256) void k_stage1(
    const float* __restrict__ xin,  const float* __restrict__ freqs,
    const float* __restrict__ w1,   const float* __restrict__ b1,
    const float* __restrict__ lng,  const float* __restrict__ lnb) {
    int e = blockIdx.y;
    int cnt = g_count[e];
    int base = blockIdx.x * 32;
    if (base >= cnt) return;

    __shared__ float xs[32][17];
    __shared__ float feat_s[33][32];
    __shared__ float red[8][8][2];

    int tid = threadIdx.x;
    int cg = tid & 63;          // col group: cols cg*8 .. cg*8+7
    int rg = tid >> 6;          // row group: slots rg*8 .. rg*8+7
    int warp = tid >> 5, lane = tid & 31;

    if (tid < 32) {
        int s = base + tid;
        int row = (s < cnt) ? g_rows[e * NB + s] : g_rows[e * NB];
        const float4* xr = (const float4*)(xin + (size_t)row * ND);
        float4 v0 = xr[0], v1 = xr[1], v2 = xr[2], v3 = xr[3];
        xs[tid][0] = v0.x; xs[tid][1] = v0.y; xs[tid][2] = v0.z; xs[tid][3] = v0.w;
        xs[tid][4] = v1.x; xs[tid][5] = v1.y; xs[tid][6] = v1.z; xs[tid][7] = v1.w;
        xs[tid][8] = v2.x; xs[tid][9] = v2.y; xs[tid][10] = v2.z; xs[tid][11] = v2.w;
        xs[tid][12] = v3.x; xs[tid][13] = v3.y; xs[tid][14] = v3.z; xs[tid][15] = v3.w;
    }

    float4 accA[8], accB[8];
#pragma unroll
    for (int i = 0; i < 8; i++) {
        accA[i] = make_float4(0.f, 0.f, 0.f, 0.f);
        accB[i] = make_float4(0.f, 0.f, 0.f, 0.f);
    }

    const float* w1e   = w1 + (size_t)e * ND * 33 * NH;
    const float* freqe = freqs + (size_t)e * ND * NF;

#pragma unroll 1
    for (int d = 0; d < ND; d++) {
        __syncthreads();
        // feat[k][slot]: k<16 cos, 16..31 sin, 32 identity
#pragma unroll 1
        for (int idx = tid; idx < 512; idx += 256) {
            int k = idx >> 5, s = idx & 31;
            float ang = xs[s][d] * __ldg(&freqe[d * NF + k]) * TWO_PI;
            float sv, cv;
            sincosf(ang, &sv, &cv);
            feat_s[k][s] = cv;
            feat_s[16 + k][s] = sv;
        }
        if (tid < 32) feat_s[32][tid] = xs[tid][d];
        __syncthreads();

        const float*  w1d = w1e + (size_t)d * 33 * NH;
        const float4* b1d = (const float4*)(b1 + (size_t)(e * ND + d) * NH);
        float4 bA = __ldg(b1d + cg * 2), bB = __ldg(b1d + cg * 2 + 1);
        float4 hA[8], hB[8];
#pragma unroll
        for (int i = 0; i < 8; i++) { hA[i] = bA; hB[i] = bB; }

#pragma unroll 3
        for (int k = 0; k < 33; k++) {
            const float4* wr = (const float4*)(w1d + (size_t)k * NH);
            float4 wA = __ldg(wr + cg * 2);
            float4 wB = __ldg(wr + cg * 2 + 1);
            float4 fA = *(const float4*)&feat_s[k][rg * 8];
            float4 fB = *(const float4*)&feat_s[k][rg * 8 + 4];
            float fs[8] = { fA.x, fA.y, fA.z, fA.w, fB.x, fB.y, fB.z, fB.w };
#pragma unroll
            for (int i = 0; i < 8; i++) {
                hA[i].x += fs[i] * wA.x; hA[i].y += fs[i] * wA.y;
                hA[i].z += fs[i] * wA.z; hA[i].w += fs[i] * wA.w;
                hB[i].x += fs[i] * wB.x; hB[i].y += fs[i] * wB.y;
                hB[i].z += fs[i] * wB.z; hB[i].w += fs[i] * wB.w;
            }
        }

        // LN stats: partial sums over this thread's 8 cols per slot
        float s1[8], s2[8];
#pragma unroll
        for (int i = 0; i < 8; i++) {
            s1[i] = hA[i].x + hA[i].y + hA[i].z + hA[i].w
                  + hB[i].x + hB[i].y + hB[i].z + hB[i].w;
            s2[i] = hA[i].x * hA[i].x + hA[i].y * hA[i].y + hA[i].z * hA[i].z + hA[i].w * hA[i].w
                  + hB[i].x * hB[i].x + hB[i].y * hB[i].y + hB[i].z * hB[i].z + hB[i].w * hB[i].w;
        }
#pragma unroll
        for (int o = 16; o > 0; o >>= 1) {
#pragma unroll
            for (int i = 0; i < 8; i++) {
                s1[i] += __shfl_xor_sync(0xffffffffu, s1[i], o);
                s2[i] += __shfl_xor_sync(0xffffffffu, s2[i], o);
            }
        }
        if (lane < 8) {
            red[warp][lane][0] = s1[lane];
            red[warp][lane][1] = s2[lane];
        }
        __syncthreads();

        const float4* gd = (const float4*)(lng + (size_t)(e * ND + d) * NH);
        const float4* od = (const float4*)(lnb + (size_t)(e * ND + d) * NH);
        float4 gA = __ldg(gd + cg * 2), gB = __ldg(gd + cg * 2 + 1);
        float4 oA = __ldg(od + cg * 2), oB = __ldg(od + cg * 2 + 1);

#pragma unroll
        for (int i = 0; i < 8; i++) {
            float ts = red[rg * 2][i][0] + red[rg * 2 + 1][i][0];
            float tq = red[rg * 2][i][1] + red[rg * 2 + 1][i][1];
            float mu  = ts * (1.0f / NH);
            float var = tq * (1.0f / NH) - mu * mu;
            float rstd = rsqrtf(var + 1e-5f);
            accA[i].x += gelu_exact((hA[i].x - mu) * rstd * gA.x + oA.x);
            accA[i].y += gelu_exact((hA[i].y - mu) * rstd * gA.y + oA.y);
            accA[i].z += gelu_exact((hA[i].z - mu) * rstd * gA.z + oA.z);
            accA[i].w += gelu_exact((hA[i].w - mu) * rstd * gA.w + oA.w);
            accB[i].x += gelu_exact((hB[i].x - mu) * rstd * gB.x + oB.x);
            accB[i].y += gelu_exact((hB[i].y - mu) * rstd * gB.y + oB.y);
            accB[i].z += gelu_exact((hB[i].z - mu) * rstd * gB.z + oB.z);
            accB[i].w += gelu_exact((hB[i].w - mu) * rstd * gB.w + oB.w);
        }
    }

#pragma unroll
    for (int i = 0; i < 8; i++) {
        int s = base + rg * 8 + i;
        if (s < cnt) {
            float4* dst = (float4*)(g_mid + (size_t)(e * NB + s) * NH) + cg * 2;
            dst[0] = accA[i];
            dst[1] = accB[i];
        }
    }
}

// ---------------- stage 2: per-expert GEMM mid[cnt,512] @ wo[512,512], scatter
// 128x128x16 tile, 256 threads, 8x8 micro-tile. Outer k0-loop rolled.
#define BM 128
#define BN 128
#define BK 16
__global__ __launch_bounds__(256) void k_stage2(
    const float* __restrict__ wo, const float* __restrict__ bo,
    float* __restrict__ out) {
    int e = blockIdx.z;
    int cnt = g_count[e];
    int rowbase = blockIdx.x * BM;
    if (rowbase >= cnt) return;
    int colbase = blockIdx.y * BN;

    __shared__ float As[BK][BM + 4];
    __shared__ float Bs[BK][BN];

    int tid = threadIdx.x;
    int tx = tid & 15;          // col group: cols tx*8 .. +8
    int ty = tid >> 4;          // row group: rows ty*8 .. +8

    float4 cA[8], cB[8];
#pragma unroll
    for (int i = 0; i < 8; i++) {
        cA[i] = make_float4(0.f, 0.f, 0.f, 0.f);
        cB[i] = make_float4(0.f, 0.f, 0.f, 0.f);
    }

    const float* mide = g_mid + (size_t)e * NB * NH;
    const float* woe  = wo + (size_t)e * NH * NH;

#pragma unroll 1
    for (int k0 = 0; k0 < NH; k0 += BK) {
        // stage A (transposed), zero-fill beyond cnt
#pragma unroll
        for (int q = 0; q < 2; q++) {
            int idx = tid + q * 256;
            int r = idx >> 2, kq = idx & 3;
            int gr = rowbase + r;
            float4 v = make_float4(0.f, 0.f, 0.f, 0.f);
            if (gr < cnt)
                v = *(const float4*)(mide + (size_t)gr * NH + k0 + kq * 4);
            As[kq * 4 + 0][r] = v.x;
            As[kq * 4 + 1][r] = v.y;
            As[kq * 4 + 2][r] = v.z;
            As[kq * 4 + 3][r] = v.w;
        }
        // stage B
#pragma unroll
        for (int q = 0; q < 2; q++) {
            int idx = tid + q * 256;
            int c4 = idx & 31, kk = idx >> 5;
            *(float4*)&Bs[kk][c4 * 4] =
                *(const float4*)(woe + (size_t)(k0 + kk) * NH + colbase + c4 * 4);
        }
        __syncthreads();

#pragma unroll
        for (int kk = 0; kk < BK; kk++) {
            float4 a0 = *(const float4*)&As[kk][ty * 8];
            float4 a1 = *(const float4*)&As[kk][ty * 8 + 4];
            float4 b0 = *(const float4*)&Bs[kk][tx * 8];
            float4 b1 = *(const float4*)&Bs[kk][tx * 8 + 4];
            float ar[8] = { a0.x, a0.y, a0.z, a0.w, a1.x, a1.y, a1.z, a1.w };
#pragma unroll
            for (int i = 0; i < 8; i++) {
                cA[i].x += ar[i] * b0.x; cA[i].y += ar[i] * b0.y;
                cA[i].z += ar[i] * b0.z; cA[i].w += ar[i] * b0.w;
                cB[i].x += ar[i] * b1.x; cB[i].y += ar[i] * b1.y;
                cB[i].z += ar[i] * b1.z; cB[i].w += ar[i] * b1.w;
            }
        }
        __syncthreads();
    }

    const float4* bop = (const float4*)(bo + (size_t)e * NH + colbase);
    float4 boA = __ldg(bop + tx * 2);
    float4 boB = __ldg(bop + tx * 2 + 1);
#pragma unroll
    for (int i = 0; i < 8; i++) {
        int s = rowbase + ty * 8 + i;
        if (s < cnt) {
            int b = g_rows[e * NB + s];
            float g = g_gate[e * NB + s];
            float* o = out + (size_t)b * NH + colbase + tx * 8;
            atomicAdd(o + 0, g * (cA[i].x + boA.x));
            atomicAdd(o + 1, g * (cA[i].y + boA.y));
            atomicAdd(o + 2, g * (cA[i].z + boA.z));
            atomicAdd(o + 3, g * (cA[i].w + boA.w));
            atomicAdd(o + 4, g * (cB[i].x + boB.x));
            atomicAdd(o + 5, g * (cB[i].y + boB.y));
            atomicAdd(o + 6, g * (cB[i].z + boB.z));
            atomicAdd(o + 7, g * (cB[i].w + boB.w));
        }
    }
}

// ---------------- launch ----------------
extern "C" void kernel_launch(void* const* d_in, const int* in_sizes, int n_in,
                              void* d_out, int out_size) {
    const float* gate_input   = (const float*)d_in[0];
    const float* expert_input = (const float*)d_in[1];
    const int*   task_bh      = (const int*)  d_in[2];
    const float* gate_w       = (const float*)d_in[3];
    const float* gate_b       = (const float*)d_in[4];
    const float* freqs        = (const float*)d_in[5];
    const float* w1           = (const float*)d_in[6];
    const float* b1           = (const float*)d_in[7];
    const float* ln_g         = (const float*)d_in[8];
    const float* ln_b         = (const float*)d_in[9];
    const float* wo           = (const float*)d_in[10];
    const float* bo           = (const float*)d_in[11];
    float* out = (float*)d_out;

    k_init<<<2048, 256>>>(out, out_size);
    k_gate<<<NB / 256, 256>>>(gate_input, task_bh, gate_w, gate_b);
    k_stage1<<<dim3(NB / 32, NE), 256>>>(expert_input, freqs, w1, b1, ln_g, ln_b);
    k_stage2<<<dim3(NB / BM, NH / BN, NE), 256>>>(wo, bo, out);
}

// round 9
// speedup vs baseline: 1.1286x; 1.0077x over previous
#include <cuda_runtime.h>
#include <math.h>

#define NE 8      // experts
#define ND 16     // robot_state_size
#define NF 16     // freq bands
#define NH 512    // hidden
#define NG 16     // gate input
#define NB 8192   // batch
#define TWO_PI 6.283185307179586f

// ---------------- device scratch (no dynamic alloc allowed) ----------------
__device__ int   g_count[NE];
__device__ int   g_rows[NE * NB];
__device__ float g_gate[NE * NB];
__device__ __align__(16) float g_mid[(size_t)NE * NB * NH];   // 128 MB

__device__ __forceinline__ float gelu_exact(float x) {
    return 0.5f * x * (1.0f + erff(x * 0.70710678118654752f));
}

// ---------------- init: zero output buffer + expert counters ----------------
__global__ void k_init(float* __restrict__ out, int out_size) {
    int idx = blockIdx.x * blockDim.x + threadIdx.x;
    if (idx < NE) g_count[idx] = 0;
    for (int i = idx; i < out_size; i += gridDim.x * blockDim.x)
        out[i] = 0.0f;
}

// ---------------- gate: logits -> softmax -> top2 -> renorm -> scatter ------
__global__ void k_gate(const float* __restrict__ gin, const int* __restrict__ task_p,
                       const float* __restrict__ gw, const float* __restrict__ gb) {
    __shared__ float sw[NG * NE];
    __shared__ float sb[NE];
    int task = task_p[0];
    for (int i = threadIdx.x; i < NG * NE; i += blockDim.x)
        sw[i] = gw[task * NG * NE + i];
    if (threadIdx.x < NE) sb[threadIdx.x] = gb[task * NE + threadIdx.x];
    __syncthreads();

    int b = blockIdx.x * blockDim.x + threadIdx.x;
    if (b >= NB) return;

    float x[NG];
#pragma unroll
    for (int g = 0; g < NG; g++) x[g] = gin[b * NG + g];

    float lg[NE];
#pragma unroll
    for (int e = 0; e < NE; e++) {
        float s = sb[e];
#pragma unroll
        for (int g = 0; g < NG; g++) s += x[g] * sw[g * NE + e];
        lg[e] = s;
    }
    float m = lg[0];
#pragma unroll
    for (int e = 1; e < NE; e++) m = fmaxf(m, lg[e]);
    float p[NE];
#pragma unroll
    for (int e = 0; e < NE; e++) p[e] = expf(lg[e] - m);

    // top-2 (ties -> lower index, matching lax.top_k)
    int i0 = 0; float v0 = p[0];
#pragma unroll
    for (int e = 1; e < NE; e++) if (p[e] > v0) { v0 = p[e]; i0 = e; }
    int i1 = (i0 == 0) ? 1 : 0; float v1 = p[i1];
#pragma unroll
    for (int e = 0; e < NE; e++) if (e != i0 && p[e] > v1) { v1 = p[e]; i1 = e; }

    float inv = 1.0f / (v0 + v1);   // softmax denom cancels in the ratio
    v0 *= inv; v1 *= inv;

    int p0 = atomicAdd(&g_count[i0], 1);
    g_rows[i0 * NB + p0] = b; g_gate[i0 * NB + p0] = v0;
    int p1 = atomicAdd(&g_count[i1], 1);
    g_rows[i1 * NB + p1] = b; g_gate[i1 * NB + p1] = v1;
}

// ---------------- stage 1: fourier feat -> per-dim linear -> LN -> gelu -> sum_d
// Block = 4 independent warp-pairs; each pair owns 8 slots x 512 cols.
// Thread owns cols [cg*4,+4) and [256+cg*4,+4)  (contiguous lane->addr maps).
// Pairs sync only via named barriers -> no block-wide coupling in the d-loop.
__global__ __launch_bounds__(256) void k_stage1(
    const float* __restrict__ xin,  const float* __restrict__ freqs,
    const float* __restrict__ w1,   const float* __restrict__ b1,
    const float* __restrict__ lng,  const float* __restrict__ lnb) {
    int e = blockIdx.y;
    int cnt = g_count[e];
    int base = blockIdx.x * 32;
    if (base >= cnt) return;

    __shared__ float xs[32][17];
    __shared__ __align__(16) float feat_p[4][33][8];   // per-pair feature tile
    __shared__ float red[4][2][8][2];

    int tid = threadIdx.x;
    int cg = tid & 63;          // 0..63 within pair
    int rg = tid >> 6;          // pair id 0..3 (slots rg*8..rg*8+7)
    int lane = tid & 31;
    int whalf = (tid >> 5) & 1; // which warp of the pair

    if (tid < 32) {
        int s = base + tid;
        int row = (s < cnt) ? g_rows[e * NB + s] : g_rows[e * NB];
        const float4* xr = (const float4*)(xin + (size_t)row * ND);
        float4 v0 = xr[0], v1 = xr[1], v2 = xr[2], v3 = xr[3];
        xs[tid][0] = v0.x; xs[tid][1] = v0.y; xs[tid][2] = v0.z; xs[tid][3] = v0.w;
        xs[tid][4] = v1.x; xs[tid][5] = v1.y; xs[tid][6] = v1.z; xs[tid][7] = v1.w;
        xs[tid][8] = v2.x; xs[tid][9] = v2.y; xs[tid][10] = v2.z; xs[tid][11] = v2.w;
        xs[tid][12] = v3.x; xs[tid][13] = v3.y; xs[tid][14] = v3.z; xs[tid][15] = v3.w;
    }
    __syncthreads();            // once, before the d-loop

    float4 accA[8], accB[8];
#pragma unroll
    for (int i = 0; i < 8; i++) {
        accA[i] = make_float4(0.f, 0.f, 0.f, 0.f);
        accB[i] = make_float4(0.f, 0.f, 0.f, 0.f);
    }

    const float* w1e   = w1 + (size_t)e * ND * 33 * NH;
    const float* freqe = freqs + (size_t)e * ND * NF;

#pragma unroll 1
    for (int d = 0; d < ND; d++) {
        // ---- build this pair's feat[33][8] ----
        {
            int t = cg;
#pragma unroll
            for (int it = 0; it < 2; it++) {
                int k = t >> 3, j = t & 7;          // k in 0..15
                float ang = xs[rg * 8 + j][d] * __ldg(&freqe[d * NF + k]) * TWO_PI;
                float sv, cv;
                sincosf(ang, &sv, &cv);
                feat_p[rg][k][j] = cv;
                feat_p[rg][16 + k][j] = sv;
                t += 64;
            }
            if (cg < 8) feat_p[rg][32][cg] = xs[rg * 8 + cg][d];
        }
        asm volatile("bar.sync %0, %1;" :: "r"(rg + 1), "r"(64) : "memory");

        const float*  w1d  = w1e + (size_t)d * 33 * NH;
        const float4* b1d4 = (const float4*)(b1 + (size_t)(e * ND + d) * NH);
        float4 bA = __ldg(b1d4 + cg), bB = __ldg(b1d4 + 64 + cg);
        float4 hA[8], hB[8];
#pragma unroll
        for (int i = 0; i < 8; i++) { hA[i] = bA; hB[i] = bB; }

#pragma unroll 3
        for (int k = 0; k < 33; k++) {
            const float4* wr = (const float4*)(w1d + (size_t)k * NH);
            float4 wA = __ldg(wr + cg);         // contiguous 512B per warp
            float4 wB = __ldg(wr + 64 + cg);    // contiguous 512B per warp
            float4 fA = *(const float4*)&feat_p[rg][k][0];
            float4 fB = *(const float4*)&feat_p[rg][k][4];
            float fs[8] = { fA.x, fA.y, fA.z, fA.w, fB.x, fB.y, fB.z, fB.w };
#pragma unroll
            for (int i = 0; i < 8; i++) {
                hA[i].x += fs[i] * wA.x; hA[i].y += fs[i] * wA.y;
                hA[i].z += fs[i] * wA.z; hA[i].w += fs[i] * wA.w;
                hB[i].x += fs[i] * wB.x; hB[i].y += fs[i] * wB.y;
                hB[i].z += fs[i] * wB.z; hB[i].w += fs[i] * wB.w;
            }
        }

        // ---- LN stats across the pair (64 threads own the 512 cols) ----
        float s1[8], s2[8];
#pragma unroll
        for (int i = 0; i < 8; i++) {
            s1[i] = hA[i].x + hA[i].y + hA[i].z + hA[i].w
                  + hB[i].x + hB[i].y + hB[i].z + hB[i].w;
            s2[i] = hA[i].x * hA[i].x + hA[i].y * hA[i].y + hA[i].z * hA[i].z + hA[i].w * hA[i].w
                  + hB[i].x * hB[i].x + hB[i].y * hB[i].y + hB[i].z * hB[i].z + hB[i].w * hB[i].w;
        }
#pragma unroll
        for (int o = 16; o > 0; o >>= 1) {
#pragma unroll
            for (int i = 0; i < 8; i++) {
                s1[i] += __shfl_xor_sync(0xffffffffu, s1[i], o);
                s2[i] += __shfl_xor_sync(0xffffffffu, s2[i], o);
            }
        }
        if (lane < 8) {
            red[rg][whalf][lane][0] = s1[lane];
            red[rg][whalf][lane][1] = s2[lane];
        }
        asm volatile("bar.sync %0, %1;" :: "r"(rg + 1), "r"(64) : "memory");

        const float4* gd = (const float4*)(lng + (size_t)(e * ND + d) * NH);
        const float4* od = (const float4*)(lnb + (size_t)(e * ND + d) * NH);
        float4 gA = __ldg(gd + cg), gB = __ldg(gd + 64 + cg);
        float4 oA = __ldg(od + cg), oB = __ldg(od + 64 + cg);

#pragma unroll
        for (int i = 0; i < 8; i++) {
            float ts = red[rg][0][i][0] + red[rg][1][i][0];
            float tq = red[rg][0][i][1] + red[rg][1][i][1];
            float mu  = ts * (1.0f / NH);
            float var = tq * (1.0f / NH) - mu * mu;
            float rstd = rsqrtf(var + 1e-5f);
            accA[i].x += gelu_exact((hA[i].x - mu) * rstd * gA.x + oA.x);
            accA[i].y += gelu_exact((hA[i].y - mu) * rstd * gA.y + oA.y);
            accA[i].z += gelu_exact((hA[i].z - mu) * rstd * gA.z + oA.z);
            accA[i].w += gelu_exact((hA[i].w - mu) * rstd * gA.w + oA.w);
            accB[i].x += gelu_exact((hB[i].x - mu) * rstd * gB.x + oB.x);
            accB[i].y += gelu_exact((hB[i].y - mu) * rstd * gB.y + oB.y);
            accB[i].z += gelu_exact((hB[i].z - mu) * rstd * gB.z + oB.z);
            accB[i].w += gelu_exact((hB[i].w - mu) * rstd * gB.w + oB.w);
        }
    }

#pragma unroll
    for (int i = 0; i < 8; i++) {
        int s = base + rg * 8 + i;
        if (s < cnt) {
            float4* dst = (float4*)(g_mid + (size_t)(e * NB + s) * NH);
            dst[cg]      = accA[i];
            dst[64 + cg] = accB[i];
        }
    }
}

// ---------------- stage 2: per-expert GEMM mid[cnt,512] @ wo[512,512], scatter
// 128x128x16 tile, 256 threads, 8x8 micro-tile (split-half cols -> no LDS
// conflicts), register-prefetch pipeline on the k-loop.
#define BM 128
#define BN 128
#define BK 16
__global__ __launch_bounds__(256, 2) void k_stage2(
    const float* __restrict__ wo, const float* __restrict__ bo,
    float* __restrict__ out) {
    int e = blockIdx.z;
    int cnt = g_count[e];
    int rowbase = blockIdx.x * BM;
    if (rowbase >= cnt) return;
    int colbase = blockIdx.y * BN;

    __shared__ float As[BK][BM + 4];
    __shared__ float Bs[BK][BN];

    int tid = threadIdx.x;
    int tx = tid & 15;          // cols: [tx*4,+4) and [64+tx*4,+4)
    int ty = tid >> 4;          // rows: ty*8 .. +8

    float4 cA[8], cB[8];
#pragma unroll
    for (int i = 0; i < 8; i++) {
        cA[i] = make_float4(0.f, 0.f, 0.f, 0.f);
        cB[i] = make_float4(0.f, 0.f, 0.f, 0.f);
    }

    const float* mide = g_mid + (size_t)e * NB * NH;
    const float* woe  = wo + (size_t)e * NH * NH;

    // prefetch registers for the k-tile loads
    float4 pa[2], pb[2];
    const int a_r  = (tid << 1) >> 3;       // unused helper removed below
#pragma unroll
    for (int q = 0; q < 2; q++) {
        int idx = tid + q * 256;
        int r = idx >> 2, kq = idx & 3;
        int gr = rowbase + r;
        pa[q] = (gr < cnt) ? *(const float4*)(mide + (size_t)gr * NH + kq * 4)
                           : make_float4(0.f, 0.f, 0.f, 0.f);
        int c4 = idx & 31, kb = idx >> 5;
        pb[q] = *(const float4*)(woe + (size_t)kb * NH + colbase + c4 * 4);
    }

#pragma unroll 1
    for (int k0 = 0; k0 < NH; k0 += BK) {
        // commit prefetched tile to smem
#pragma unroll
        for (int q = 0; q < 2; q++) {
            int idx = tid + q * 256;
            int r = idx >> 2, kq = idx & 3;
            As[kq * 4 + 0][r] = pa[q].x;
            As[kq * 4 + 1][r] = pa[q].y;
            As[kq * 4 + 2][r] = pa[q].z;
            As[kq * 4 + 3][r] = pa[q].w;
            int c4 = idx & 31, kb = idx >> 5;
            *(float4*)&Bs[kb][c4 * 4] = pb[q];
        }
        __syncthreads();

        // issue next tile's loads (overlap with FMA block)
        int k1 = k0 + BK;
        if (k1 < NH) {
#pragma unroll
            for (int q = 0; q < 2; q++) {
                int idx = tid + q * 256;
                int r = idx >> 2, kq = idx & 3;
                int gr = rowbase + r;
                pa[q] = (gr < cnt) ? *(const float4*)(mide + (size_t)gr * NH + k1 + kq * 4)
                                   : make_float4(0.f, 0.f, 0.f, 0.f);
                int c4 = idx & 31, kb = idx >> 5;
                pb[q] = *(const float4*)(woe + (size_t)(k1 + kb) * NH + colbase + c4 * 4);
            }
        }

#pragma unroll
        for (int kk = 0; kk < BK; kk++) {
            float4 a0 = *(const float4*)&As[kk][ty * 8];
            float4 a1 = *(const float4*)&As[kk][ty * 8 + 4];
            float4 b0 = *(const float4*)&Bs[kk][tx * 4];        // contiguous
            float4 b1 = *(const float4*)&Bs[kk][64 + tx * 4];   // contiguous
            float ar[8] = { a0.x, a0.y, a0.z, a0.w, a1.x, a1.y, a1.z, a1.w };
#pragma unroll
            for (int i = 0; i < 8; i++) {
                cA[i].x += ar[i] * b0.x; cA[i].y += ar[i] * b0.y;
                cA[i].z += ar[i] * b0.z; cA[i].w += ar[i] * b0.w;
                cB[i].x += ar[i] * b1.x; cB[i].y += ar[i] * b1.y;
                cB[i].z += ar[i] * b1.z; cB[i].w += ar[i] * b1.w;
            }
        }
        __syncthreads();
    }

    const float4* bop = (const float4*)(bo + (size_t)e * NH + colbase);
    float4 boA = __ldg(bop + tx);
    float4 boB = __ldg(bop + 16 + tx);
#pragma unroll
    for (int i = 0; i < 8; i++) {
        int s = rowbase + ty * 8 + i;
        if (s < cnt) {
            int b = g_rows[e * NB + s];
            float g = g_gate[e * NB + s];
            float* o = out + (size_t)b * NH + colbase;
            atomicAdd(o + tx * 4 + 0, g * (cA[i].x + boA.x));
            atomicAdd(o + tx * 4 + 1, g * (cA[i].y + boA.y));
            atomicAdd(o + tx * 4 + 2, g * (cA[i].z + boA.z));
            atomicAdd(o + tx * 4 + 3, g * (cA[i].w + boA.w));
            atomicAdd(o + 64 + tx * 4 + 0, g * (cB[i].x + boB.x));
            atomicAdd(o + 64 + tx * 4 + 1, g * (cB[i].y + boB.y));
            atomicAdd(o + 64 + tx * 4 + 2, g * (cB[i].z + boB.z));
            atomicAdd(o + 64 + tx * 4 + 3, g * (cB[i].w + boB.w));
        }
    }
}

// ---------------- launch ----------------
extern "C" void kernel_launch(void* const* d_in, const int* in_sizes, int n_in,
                              void* d_out, int out_size) {
    const float* gate_input   = (const float*)d_in[0];
    const float* expert_input = (const float*)d_in[1];
    const int*   task_bh      = (const int*)  d_in[2];
    const float* gate_w       = (const float*)d_in[3];
    const float* gate_b       = (const float*)d_in[4];
    const float* freqs        = (const float*)d_in[5];
    const float* w1           = (const float*)d_in[6];
    const float* b1           = (const float*)d_in[7];
    const float* ln_g         = (const float*)d_in[8];
    const float* ln_b         = (const float*)d_in[9];
    const float* wo           = (const float*)d_in[10];
    const float* bo           = (const float*)d_in[11];
    float* out = (float*)d_out;

    k_init<<<2048, 256>>>(out, out_size);
    k_gate<<<NB / 256, 256>>>(gate_input, task_bh, gate_w, gate_b);
    k_stage1<<<dim3(NB / 32, NE), 256>>>(expert_input, freqs, w1, b1, ln_g, ln_b);
    k_stage2<<<dim3(NB / BM, NH / BN, NE), 256>>>(wo, bo, out);
}

// round 10
// speedup vs baseline: 1.7481x; 1.5489x over previous
#include <cuda_runtime.h>
#include <math.h>

#define NE 8      // experts
#define ND 16     // robot_state_size
#define NF 16     // freq bands
#define NH 512    // hidden
#define NG 16     // gate input
#define NB 8192   // batch
#define TWO_PI 6.283185307179586f

// ---------------- device scratch (no dynamic alloc allowed) ----------------
__device__ int   g_count[NE];
__device__ int   g_rows[NE * NB];
__device__ float g_gate[NE * NB];
__device__ __align__(16) float g_mid[(size_t)NE * NB * NH];   // 128 MB

// Abramowitz-Stegun 7.1.26 erf (|abs err| <= 1.5e-7) -> exact-gelu to ~1e-6
__device__ __forceinline__ float fast_gelu(float x) {
    float u = 0.70710678118654752f * x;
    float a = fabsf(u);
    float t = __fdividef(1.0f, fmaf(0.3275911f, a, 1.0f));
    float poly = t * fmaf(t, fmaf(t, fmaf(t, fmaf(t, 1.061405429f, -1.453152027f),
                                          1.421413741f), -0.284496736f), 0.254829592f);
    float e = __expf(-u * u);
    float erfa = fmaf(-poly, e, 1.0f);
    float erfu = copysignf(erfa, x);
    return 0.5f * x * (1.0f + erfu);
}

// ---------------- init: zero output buffer + expert counters ----------------
__global__ void k_init(float* __restrict__ out, int out_size) {
    int idx = blockIdx.x * blockDim.x + threadIdx.x;
    if (idx < NE) g_count[idx] = 0;
    int n4 = out_size >> 2;
    float4* o4 = (float4*)out;
    for (int i = idx; i < n4; i += gridDim.x * blockDim.x)
        o4[i] = make_float4(0.f, 0.f, 0.f, 0.f);
    if (idx < (out_size & 3)) out[n4 * 4 + idx] = 0.0f;
}

// ---------------- gate: logits -> softmax -> top2 -> renorm -> scatter ------
__global__ void k_gate(const float* __restrict__ gin, const int* __restrict__ task_p,
                       const float* __restrict__ gw, const float* __restrict__ gb) {
    __shared__ float sw[NG * NE];
    __shared__ float sb[NE];
    int task = task_p[0];
    for (int i = threadIdx.x; i < NG * NE; i += blockDim.x)
        sw[i] = gw[task * NG * NE + i];
    if (threadIdx.x < NE) sb[threadIdx.x] = gb[task * NE + threadIdx.x];
    __syncthreads();

    int b = blockIdx.x * blockDim.x + threadIdx.x;
    if (b >= NB) return;

    float x[NG];
#pragma unroll
    for (int g = 0; g < NG; g++) x[g] = gin[b * NG + g];

    float lg[NE];
#pragma unroll
    for (int e = 0; e < NE; e++) {
        float s = sb[e];
#pragma unroll
        for (int g = 0; g < NG; g++) s += x[g] * sw[g * NE + e];
        lg[e] = s;
    }
    float m = lg[0];
#pragma unroll
    for (int e = 1; e < NE; e++) m = fmaxf(m, lg[e]);
    float p[NE];
#pragma unroll
    for (int e = 0; e < NE; e++) p[e] = expf(lg[e] - m);

    // top-2 (ties -> lower index, matching lax.top_k)
    int i0 = 0; float v0 = p[0];
#pragma unroll
    for (int e = 1; e < NE; e++) if (p[e] > v0) { v0 = p[e]; i0 = e; }
    int i1 = (i0 == 0) ? 1 : 0; float v1 = p[i1];
#pragma unroll
    for (int e = 0; e < NE; e++) if (e != i0 && p[e] > v1) { v1 = p[e]; i1 = e; }

    float inv = 1.0f / (v0 + v1);   // softmax denom cancels in the ratio
    v0 *= inv; v1 *= inv;

    int p0 = atomicAdd(&g_count[i0], 1);
    g_rows[i0 * NB + p0] = b; g_gate[i0 * NB + p0] = v0;
    int p1 = atomicAdd(&g_count[i1], 1);
    g_rows[i1 * NB + p1] = b; g_gate[i1 * NB + p1] = v1;
}

// ---------------- stage 1: fourier feat -> per-dim linear -> LN -> gelu -> sum_d
// Block = 4 independent 64-thread pairs; each pair owns 4 slots x 512 cols.
// Thread: 4 slots x 8 cols (split halves: cols [cg*4,+4) and [256+cg*4,+4)).
// ~110 regs -> 2 CTAs/SM (16 warps) for latency hiding.
__global__ __launch_bounds__(256, 2) void k_stage1(
    const float* __restrict__ xin,  const float* __restrict__ freqs,
    const float* __restrict__ w1,   const float* __restrict__ b1,
    const float* __restrict__ lng,  const float* __restrict__ lnb) {
    int e = blockIdx.y;
    int cnt = g_count[e];
    int base = blockIdx.x * 16;
    if (base >= cnt) return;

    __shared__ float xs[16][17];
    __shared__ __align__(16) float feat_p[4][33][4];   // per-pair: 33 x 4 slots
    __shared__ float red[4][2][4][2];

    int tid = threadIdx.x;
    int cg = tid & 63;          // 0..63 within pair
    int rg = tid >> 6;          // pair id 0..3 (slots rg*4..rg*4+3)
    int lane = tid & 31;
    int whalf = (tid >> 5) & 1; // which warp of the pair

    if (tid < 16) {
        int s = base + tid;
        int row = (s < cnt) ? g_rows[e * NB + s] : g_rows[e * NB];
        const float4* xr = (const float4*)(xin + (size_t)row * ND);
        float4 v0 = xr[0], v1 = xr[1], v2 = xr[2], v3 = xr[3];
        xs[tid][0] = v0.x; xs[tid][1] = v0.y; xs[tid][2] = v0.z; xs[tid][3] = v0.w;
        xs[tid][4] = v1.x; xs[tid][5] = v1.y; xs[tid][6] = v1.z; xs[tid][7] = v1.w;
        xs[tid][8] = v2.x; xs[tid][9] = v2.y; xs[tid][10] = v2.z; xs[tid][11] = v2.w;
        xs[tid][12] = v3.x; xs[tid][13] = v3.y; xs[tid][14] = v3.z; xs[tid][15] = v3.w;
    }
    __syncthreads();            // once, before the d-loop

    float4 accA[4], accB[4];
#pragma unroll
    for (int i = 0; i < 4; i++) {
        accA[i] = make_float4(0.f, 0.f, 0.f, 0.f);
        accB[i] = make_float4(0.f, 0.f, 0.f, 0.f);
    }

    const float* w1e   = w1 + (size_t)e * ND * 33 * NH;
    const float* freqe = freqs + (size_t)e * ND * NF;

#pragma unroll 1
    for (int d = 0; d < ND; d++) {
        // ---- build this pair's feat[33][4]: 64 threads cover 16k x 4j ----
        {
            int k = cg >> 2, j = cg & 3;
            float xv = xs[rg * 4 + j][d];
            float ang = xv * __ldg(&freqe[d * NF + k]) * TWO_PI;
            float sv, cv;
            __sincosf(ang, &sv, &cv);
            feat_p[rg][k][j] = cv;
            feat_p[rg][16 + k][j] = sv;
            if (cg < 4) feat_p[rg][32][cg] = xs[rg * 4 + cg][d];
        }
        asm volatile("bar.sync %0, %1;" :: "r"(rg + 1), "r"(64) : "memory");

        const float*  w1d  = w1e + (size_t)d * 33 * NH;
        const float4* b1d4 = (const float4*)(b1 + (size_t)(e * ND + d) * NH);
        float4 bA = __ldg(b1d4 + cg), bB = __ldg(b1d4 + 64 + cg);
        float4 hA[4], hB[4];
#pragma unroll
        for (int i = 0; i < 4; i++) { hA[i] = bA; hB[i] = bB; }

#pragma unroll 3
        for (int k = 0; k < 33; k++) {
            const float4* wr = (const float4*)(w1d + (size_t)k * NH);
            float4 wA = __ldg(wr + cg);         // contiguous 512B per warp
            float4 wB = __ldg(wr + 64 + cg);
            float4 f4 = *(const float4*)&feat_p[rg][k][0];   // broadcast
            float fs[4] = { f4.x, f4.y, f4.z, f4.w };
#pragma unroll
            for (int i = 0; i < 4; i++) {
                hA[i].x += fs[i] * wA.x; hA[i].y += fs[i] * wA.y;
                hA[i].z += fs[i] * wA.z; hA[i].w += fs[i] * wA.w;
                hB[i].x += fs[i] * wB.x; hB[i].y += fs[i] * wB.y;
                hB[i].z += fs[i] * wB.z; hB[i].w += fs[i] * wB.w;
            }
        }

        // ---- LN stats across the pair (64 threads own the 512 cols) ----
        float s1[4], s2[4];
#pragma unroll
        for (int i = 0; i < 4; i++) {
            s1[i] = hA[i].x + hA[i].y + hA[i].z + hA[i].w
                  + hB[i].x + hB[i].y + hB[i].z + hB[i].w;
            s2[i] = hA[i].x * hA[i].x + hA[i].y * hA[i].y + hA[i].z * hA[i].z + hA[i].w * hA[i].w
                  + hB[i].x * hB[i].x + hB[i].y * hB[i].y + hB[i].z * hB[i].z + hB[i].w * hB[i].w;
        }
#pragma unroll
        for (int o = 16; o > 0; o >>= 1) {
#pragma unroll
            for (int i = 0; i < 4; i++) {
                s1[i] += __shfl_xor_sync(0xffffffffu, s1[i], o);
                s2[i] += __shfl_xor_sync(0xffffffffu, s2[i], o);
            }
        }
#pragma unroll
        for (int i = 0; i < 4; i++) {
            if (lane == i) {
                red[rg][whalf][i][0] = s1[i];
                red[rg][whalf][i][1] = s2[i];
            }
        }
        asm volatile("bar.sync %0, %1;" :: "r"(rg + 1), "r"(64) : "memory");

        const float4* gd = (const float4*)(lng + (size_t)(e * ND + d) * NH);
        const float4* od = (const float4*)(lnb + (size_t)(e * ND + d) * NH);
        float4 gA = __ldg(gd + cg), gB = __ldg(gd + 64 + cg);
        float4 oA = __ldg(od + cg), oB = __ldg(od + 64 + cg);

#pragma unroll
        for (int i = 0; i < 4; i++) {
            float ts = red[rg][0][i][0] + red[rg][1][i][0];
            float tq = red[rg][0][i][1] + red[rg][1][i][1];
            float mu  = ts * (1.0f / NH);
            float var = tq * (1.0f / NH) - mu * mu;
            float rstd = rsqrtf(var + 1e-5f);
            accA[i].x += fast_gelu((hA[i].x - mu) * rstd * gA.x + oA.x);
            accA[i].y += fast_gelu((hA[i].y - mu) * rstd * gA.y + oA.y);
            accA[i].z += fast_gelu((hA[i].z - mu) * rstd * gA.z + oA.z);
            accA[i].w += fast_gelu((hA[i].w - mu) * rstd * gA.w + oA.w);
            accB[i].x += fast_gelu((hB[i].x - mu) * rstd * gB.x + oB.x);
            accB[i].y += fast_gelu((hB[i].y - mu) * rstd * gB.y + oB.y);
            accB[i].z += fast_gelu((hB[i].z - mu) * rstd * gB.z + oB.z);
            accB[i].w += fast_gelu((hB[i].w - mu) * rstd * gB.w + oB.w);
        }
    }

#pragma unroll
    for (int i = 0; i < 4; i++) {
        int s = base + rg * 4 + i;
        if (s < cnt) {
            float4* dst = (float4*)(g_mid + (size_t)(e * NB + s) * NH);
            dst[cg]      = accA[i];
            dst[64 + cg] = accB[i];
        }
    }
}

// ---------------- stage 2: per-expert GEMM mid[cnt,512] @ wo[512,512], scatter
// 128x128x16 tile, 256 threads, 8x8 micro-tile, double-buffered smem
// (1 barrier per k-tile) + register prefetch.
#define BM 128
#define BN 128
#define BK 16
__global__ __launch_bounds__(256, 2) void k_stage2(
    const float* __restrict__ wo, const float* __restrict__ bo,
    float* __restrict__ out) {
    int e = blockIdx.z;
    int cnt = g_count[e];
    int rowbase = blockIdx.x * BM;
    if (rowbase >= cnt) return;
    int colbase = blockIdx.y * BN;

    __shared__ float As[2][BK][BM + 4];
    __shared__ float Bs[2][BK][BN];

    int tid = threadIdx.x;
    int tx = tid & 15;          // cols: [tx*4,+4) and [64+tx*4,+4)
    int ty = tid >> 4;          // rows: ty*8 .. +8

    float4 cA[8], cB[8];
#pragma unroll
    for (int i = 0; i < 8; i++) {
        cA[i] = make_float4(0.f, 0.f, 0.f, 0.f);
        cB[i] = make_float4(0.f, 0.f, 0.f, 0.f);
    }

    const float* mide = g_mid + (size_t)e * NB * NH;
    const float* woe  = wo + (size_t)e * NH * NH;

    // per-thread staging indices
    int a_r  = tid >> 2, a_kq = tid & 3;             // +256: r+64
    int b_c4 = tid & 31, b_kk = tid >> 5;            // +256: kk+8
    int gr0 = rowbase + a_r, gr1 = rowbase + a_r + 64;

    float4 pa[2], pb[2];
    // prologue: tile 0 -> regs -> smem[0]
    pa[0] = (gr0 < cnt) ? *(const float4*)(mide + (size_t)gr0 * NH + a_kq * 4)
                        : make_float4(0.f, 0.f, 0.f, 0.f);
    pa[1] = (gr1 < cnt) ? *(const float4*)(mide + (size_t)gr1 * NH + a_kq * 4)
                        : make_float4(0.f, 0.f, 0.f, 0.f);
    pb[0] = *(const float4*)(woe + (size_t)b_kk * NH + colbase + b_c4 * 4);
    pb[1] = *(const float4*)(woe + (size_t)(b_kk + 8) * NH + colbase + b_c4 * 4);
    {
        As[0][a_kq * 4 + 0][a_r] = pa[0].x; As[0][a_kq * 4 + 1][a_r] = pa[0].y;
        As[0][a_kq * 4 + 2][a_r] = pa[0].z; As[0][a_kq * 4 + 3][a_r] = pa[0].w;
        As[0][a_kq * 4 + 0][a_r + 64] = pa[1].x; As[0][a_kq * 4 + 1][a_r + 64] = pa[1].y;
        As[0][a_kq * 4 + 2][a_r + 64] = pa[1].z; As[0][a_kq * 4 + 3][a_r + 64] = pa[1].w;
        *(float4*)&Bs[0][b_kk][b_c4 * 4] = pb[0];
        *(float4*)&Bs[0][b_kk + 8][b_c4 * 4] = pb[1];
    }
    __syncthreads();

#pragma unroll 1
    for (int t = 0; t < NH / BK; t++) {
        int p = t & 1;
        int k1 = (t + 1) * BK;
        bool hasnext = k1 < NH;
        if (hasnext) {
            pa[0] = (gr0 < cnt) ? *(const float4*)(mide + (size_t)gr0 * NH + k1 + a_kq * 4)
                                : make_float4(0.f, 0.f, 0.f, 0.f);
            pa[1] = (gr1 < cnt) ? *(const float4*)(mide + (size_t)gr1 * NH + k1 + a_kq * 4)
                                : make_float4(0.f, 0.f, 0.f, 0.f);
            pb[0] = *(const float4*)(woe + (size_t)(k1 + b_kk) * NH + colbase + b_c4 * 4);
            pb[1] = *(const float4*)(woe + (size_t)(k1 + b_kk + 8) * NH + colbase + b_c4 * 4);
        }

#pragma unroll
        for (int kk = 0; kk < BK; kk++) {
            float4 a0 = *(const float4*)&As[p][kk][ty * 8];
            float4 a1 = *(const float4*)&As[p][kk][ty * 8 + 4];
            float4 b0 = *(const float4*)&Bs[p][kk][tx * 4];        // contiguous
            float4 b1 = *(const float4*)&Bs[p][kk][64 + tx * 4];   // contiguous
            float ar[8] = { a0.x, a0.y, a0.z, a0.w, a1.x, a1.y, a1.z, a1.w };
#pragma unroll
            for (int i = 0; i < 8; i++) {
                cA[i].x += ar[i] * b0.x; cA[i].y += ar[i] * b0.y;
                cA[i].z += ar[i] * b0.z; cA[i].w += ar[i] * b0.w;
                cB[i].x += ar[i] * b1.x; cB[i].y += ar[i] * b1.y;
                cB[i].z += ar[i] * b1.z; cB[i].w += ar[i] * b1.w;
            }
        }

        if (hasnext) {
            int q = 1 - p;
            As[q][a_kq * 4 + 0][a_r] = pa[0].x; As[q][a_kq * 4 + 1][a_r] = pa[0].y;
            As[q][a_kq * 4 + 2][a_r] = pa[0].z; As[q][a_kq * 4 + 3][a_r] = pa[0].w;
            As[q][a_kq * 4 + 0][a_r + 64] = pa[1].x; As[q][a_kq * 4 + 1][a_r + 64] = pa[1].y;
            As[q][a_kq * 4 + 2][a_r + 64] = pa[1].z; As[q][a_kq * 4 + 3][a_r + 64] = pa[1].w;
            *(float4*)&Bs[q][b_kk][b_c4 * 4] = pb[0];
            *(float4*)&Bs[q][b_kk + 8][b_c4 * 4] = pb[1];
            __syncthreads();
        }
    }

    const float4* bop = (const float4*)(bo + (size_t)e * NH + colbase);
    float4 boA = __ldg(bop + tx);
    float4 boB = __ldg(bop + 16 + tx);
#pragma unroll
    for (int i = 0; i < 8; i++) {
        int s = rowbase + ty * 8 + i;
        if (s < cnt) {
            int b = g_rows[e * NB + s];
            float g = g_gate[e * NB + s];
            float* o = out + (size_t)b * NH + colbase;
            atomicAdd(o + tx * 4 + 0, g * (cA[i].x + boA.x));
            atomicAdd(o + tx * 4 + 1, g * (cA[i].y + boA.y));
            atomicAdd(o + tx * 4 + 2, g * (cA[i].z + boA.z));
            atomicAdd(o + tx * 4 + 3, g * (cA[i].w + boA.w));
            atomicAdd(o + 64 + tx * 4 + 0, g * (cB[i].x + boB.x));
            atomicAdd(o + 64 + tx * 4 + 1, g * (cB[i].y + boB.y));
            atomicAdd(o + 64 + tx * 4 + 2, g * (cB[i].z + boB.z));
            atomicAdd(o + 64 + tx * 4 + 3, g * (cB[i].w + boB.w));
        }
    }
}

// ---------------- launch ----------------
extern "C" void kernel_launch(void* const* d_in, const int* in_sizes, int n_in,
                              void* d_out, int out_size) {
    const float* gate_input   = (const float*)d_in[0];
    const float* expert_input = (const float*)d_in[1];
    const int*   task_bh      = (const int*)  d_in[2];
    const float* gate_w       = (const float*)d_in[3];
    const float* gate_b       = (const float*)d_in[4];
    const float* freqs        = (const float*)d_in[5];
    const float* w1           = (const float*)d_in[6];
    const float* b1           = (const float*)d_in[7];
    const float* ln_g         = (const float*)d_in[8];
    const float* ln_b         = (const float*)d_in[9];
    const float* wo           = (const float*)d_in[10];
    const float* bo           = (const float*)d_in[11];
    float* out = (float*)d_out;

    k_init<<<1024, 256>>>(out, out_size);
    k_gate<<<NB / 256, 256>>>(gate_input, task_bh, gate_w, gate_b);
    k_stage1<<<dim3(NB / 16, NE), 256>>>(expert_input, freqs, w1, b1, ln_g, ln_b);
    k_stage2<<<dim3(NB / BM, NH / BN, NE), 256>>>(wo, bo, out);
}

// round 11
// speedup vs baseline: 2.0556x; 1.1759x over previous
#include <cuda_runtime.h>
#include <math.h>

#define NE 8      // experts
#define ND 16     // robot_state_size
#define NF 16     // freq bands
#define NH 512    // hidden
#define NG 16     // gate input
#define NB 8192   // batch
#define TWO_PI 6.283185307179586f

// ---------------- device scratch (no dynamic alloc allowed) ----------------
__device__ int   g_count[NE];
__device__ int   g_rows[NE * NB];
__device__ float g_gate[NE * NB];
__device__ __align__(16) float g_mid[(size_t)NE * NB * NH];   // 128 MB

// Abramowitz-Stegun 7.1.26 erf (|abs err| <= 1.5e-7) -> exact-gelu to ~1e-6
__device__ __forceinline__ float fast_gelu(float x) {
    float u = 0.70710678118654752f * x;
    float a = fabsf(u);
    float t = __fdividef(1.0f, fmaf(0.3275911f, a, 1.0f));
    float poly = t * fmaf(t, fmaf(t, fmaf(t, fmaf(t, 1.061405429f, -1.453152027f),
                                          1.421413741f), -0.284496736f), 0.254829592f);
    float e = __expf(-u * u);
    float erfa = fmaf(-poly, e, 1.0f);
    float erfu = copysignf(erfa, x);
    return 0.5f * x * (1.0f + erfu);
}

__device__ __forceinline__ unsigned f2tf32(float f) {
    unsigned r;
    asm("cvt.rna.tf32.f32 %0, %1;" : "=r"(r) : "f"(f));
    return r;
}

__device__ __forceinline__ void mma_tf32(float* c, const unsigned* a, const unsigned* b) {
    asm volatile(
        "mma.sync.aligned.m16n8k8.row.col.f32.tf32.tf32.f32 "
        "{%0,%1,%2,%3}, {%4,%5,%6,%7}, {%8,%9}, {%0,%1,%2,%3};\n"
        : "+f"(c[0]), "+f"(c[1]), "+f"(c[2]), "+f"(c[3])
        : "r"(a[0]), "r"(a[1]), "r"(a[2]), "r"(a[3]), "r"(b[0]), "r"(b[1]));
}

// ---------------- init: zero output buffer + expert counters ----------------
__global__ void k_init(float* __restrict__ out, int out_size) {
    int idx = blockIdx.x * blockDim.x + threadIdx.x;
    if (idx < NE) g_count[idx] = 0;
    int n4 = out_size >> 2;
    float4* o4 = (float4*)out;
    for (int i = idx; i < n4; i += gridDim.x * blockDim.x)
        o4[i] = make_float4(0.f, 0.f, 0.f, 0.f);
    if (idx < (out_size & 3)) out[n4 * 4 + idx] = 0.0f;
}

// ---------------- gate: logits -> softmax -> top2 -> renorm -> scatter ------
__global__ void k_gate(const float* __restrict__ gin, const int* __restrict__ task_p,
                       const float* __restrict__ gw, const float* __restrict__ gb) {
    __shared__ float sw[NG * NE];
    __shared__ float sb[NE];
    int task = task_p[0];
    for (int i = threadIdx.x; i < NG * NE; i += blockDim.x)
        sw[i] = gw[task * NG * NE + i];
    if (threadIdx.x < NE) sb[threadIdx.x] = gb[task * NE + threadIdx.x];
    __syncthreads();

    int b = blockIdx.x * blockDim.x + threadIdx.x;
    if (b >= NB) return;

    float x[NG];
#pragma unroll
    for (int g = 0; g < NG; g++) x[g] = gin[b * NG + g];

    float lg[NE];
#pragma unroll
    for (int e = 0; e < NE; e++) {
        float s = sb[e];
#pragma unroll
        for (int g = 0; g < NG; g++) s += x[g] * sw[g * NE + e];
        lg[e] = s;
    }
    float m = lg[0];
#pragma unroll
    for (int e = 1; e < NE; e++) m = fmaxf(m, lg[e]);
    float p[NE];
#pragma unroll
    for (int e = 0; e < NE; e++) p[e] = expf(lg[e] - m);

    // top-2 (ties -> lower index, matching lax.top_k)
    int i0 = 0; float v0 = p[0];
#pragma unroll
    for (int e = 1; e < NE; e++) if (p[e] > v0) { v0 = p[e]; i0 = e; }
    int i1 = (i0 == 0) ? 1 : 0; float v1 = p[i1];
#pragma unroll
    for (int e = 0; e < NE; e++) if (e != i0 && p[e] > v1) { v1 = p[e]; i1 = e; }

    float inv = 1.0f / (v0 + v1);   // softmax denom cancels in the ratio
    v0 *= inv; v1 *= inv;

    int p0 = atomicAdd(&g_count[i0], 1);
    g_rows[i0 * NB + p0] = b; g_gate[i0 * NB + p0] = v0;
    int p1 = atomicAdd(&g_count[i1], 1);
    g_rows[i1 * NB + p1] = b; g_gate[i1 * NB + p1] = v1;
}

// ---------------- stage 1: fourier feat -> per-dim linear -> LN -> gelu -> sum_d
// Block = 2 independent 128-thread quads; quad owns 8 slots x 512 cols.
// Thread: 8 slots x 4 cols -> 1 LDG.128 per k (weight reuse x8).
__global__ __launch_bounds__(256, 2) void k_stage1(
    const float* __restrict__ xin,  const float* __restrict__ freqs,
    const float* __restrict__ w1,   const float* __restrict__ b1,
    const float* __restrict__ lng,  const float* __restrict__ lnb) {
    int e = blockIdx.y;
    int cnt = g_count[e];
    int base = blockIdx.x * 16;
    if (base >= cnt) return;

    __shared__ float xs[16][17];
    __shared__ __align__(16) float feat_q[2][33][8];
    __shared__ float red[2][4][8][2];
    __shared__ float2 mur[2][8];

    int tid = threadIdx.x;
    int qid = tid >> 7;          // quad 0/1 -> slots qid*8..+7
    int qt  = tid & 127;         // col group: cols [qt*4, +4)
    int warp = (tid >> 5) & 3;   // warp within quad
    int lane = tid & 31;

    if (tid < 16) {
        int s = base + tid;
        int row = (s < cnt) ? g_rows[e * NB + s] : g_rows[e * NB];
        const float4* xr = (const float4*)(xin + (size_t)row * ND);
        float4 v0 = xr[0], v1 = xr[1], v2 = xr[2], v3 = xr[3];
        xs[tid][0] = v0.x; xs[tid][1] = v0.y; xs[tid][2] = v0.z; xs[tid][3] = v0.w;
        xs[tid][4] = v1.x; xs[tid][5] = v1.y; xs[tid][6] = v1.z; xs[tid][7] = v1.w;
        xs[tid][8] = v2.x; xs[tid][9] = v2.y; xs[tid][10] = v2.z; xs[tid][11] = v2.w;
        xs[tid][12] = v3.x; xs[tid][13] = v3.y; xs[tid][14] = v3.z; xs[tid][15] = v3.w;
    }
    __syncthreads();

    float4 acc[8];
#pragma unroll
    for (int i = 0; i < 8; i++) acc[i] = make_float4(0.f, 0.f, 0.f, 0.f);

    const float* w1e   = w1 + (size_t)e * ND * 33 * NH;
    const float* freqe = freqs + (size_t)e * ND * NF;

#pragma unroll 1
    for (int d = 0; d < ND; d++) {
        // ---- quad builds feat[33][8]: 128 threads cover 16k x 8j ----
        {
            int k = qt >> 3, j = qt & 7;
            float xv = xs[qid * 8 + j][d];
            float ang = xv * __ldg(&freqe[d * NF + k]) * TWO_PI;
            float sv, cv;
            __sincosf(ang, &sv, &cv);
            feat_q[qid][k][j] = cv;
            feat_q[qid][16 + k][j] = sv;
            if (qt < 8) feat_q[qid][32][qt] = xs[qid * 8 + qt][d];
        }
        asm volatile("bar.sync %0, %1;" :: "r"(qid + 1), "r"(128) : "memory");

        const float*  w1d  = w1e + (size_t)d * 33 * NH;
        float4 bv = __ldg((const float4*)(b1 + (size_t)(e * ND + d) * NH) + qt);
        float4 h[8];
#pragma unroll
        for (int i = 0; i < 8; i++) h[i] = bv;

#pragma unroll 3
        for (int k = 0; k < 33; k++) {
            float4 w = __ldg((const float4*)(w1d + (size_t)k * NH) + qt);  // 512B/warp
            float4 f0 = *(const float4*)&feat_q[qid][k][0];
            float4 f1 = *(const float4*)&feat_q[qid][k][4];
            float fs[8] = { f0.x, f0.y, f0.z, f0.w, f1.x, f1.y, f1.z, f1.w };
#pragma unroll
            for (int i = 0; i < 8; i++) {
                h[i].x += fs[i] * w.x; h[i].y += fs[i] * w.y;
                h[i].z += fs[i] * w.z; h[i].w += fs[i] * w.w;
            }
        }

        // ---- LN stats: 128 threads of the quad own the 512 cols ----
        float s1[8], s2[8];
#pragma unroll
        for (int i = 0; i < 8; i++) {
            s1[i] = h[i].x + h[i].y + h[i].z + h[i].w;
            s2[i] = h[i].x * h[i].x + h[i].y * h[i].y
                  + h[i].z * h[i].z + h[i].w * h[i].w;
        }
#pragma unroll
        for (int o = 16; o > 0; o >>= 1) {
#pragma unroll
            for (int i = 0; i < 8; i++) {
                s1[i] += __shfl_xor_sync(0xffffffffu, s1[i], o);
                s2[i] += __shfl_xor_sync(0xffffffffu, s2[i], o);
            }
        }
        if (lane < 8) {
            red[qid][warp][lane][0] = s1[lane];
            red[qid][warp][lane][1] = s2[lane];
        }
        asm volatile("bar.sync %0, %1;" :: "r"(qid + 1), "r"(128) : "memory");
        if (qt < 8) {
            float ts = red[qid][0][qt][0] + red[qid][1][qt][0]
                     + red[qid][2][qt][0] + red[qid][3][qt][0];
            float tq = red[qid][0][qt][1] + red[qid][1][qt][1]
                     + red[qid][2][qt][1] + red[qid][3][qt][1];
            float mu  = ts * (1.0f / NH);
            float var = tq * (1.0f / NH) - mu * mu;
            mur[qid][qt] = make_float2(mu, rsqrtf(var + 1e-5f));
        }
        asm volatile("bar.sync %0, %1;" :: "r"(qid + 1), "r"(128) : "memory");

        float4 gv = __ldg((const float4*)(lng + (size_t)(e * ND + d) * NH) + qt);
        float4 ov = __ldg((const float4*)(lnb + (size_t)(e * ND + d) * NH) + qt);

#pragma unroll
        for (int i = 0; i < 8; i++) {
            float2 m = mur[qid][i];     // broadcast LDS.64
            float mu = m.x, rstd = m.y;
            acc[i].x += fast_gelu((h[i].x - mu) * rstd * gv.x + ov.x);
            acc[i].y += fast_gelu((h[i].y - mu) * rstd * gv.y + ov.y);
            acc[i].z += fast_gelu((h[i].z - mu) * rstd * gv.z + ov.z);
            acc[i].w += fast_gelu((h[i].w - mu) * rstd * gv.w + ov.w);
        }
    }

#pragma unroll
    for (int i = 0; i < 8; i++) {
        int s = base + qid * 8 + i;
        if (s < cnt)
            ((float4*)(g_mid + (size_t)(e * NB + s) * NH))[qt] = acc[i];
    }
}

// ---------------- stage 2: per-expert GEMM via TF32 mma.sync -----------------
// 128x128x16 tile, 256 threads = 8 warps (4M x 2N), warp tile 32x64,
// double-buffered smem (tf32-converted at staging), epilogue atomic scatter.
#define BM 128
#define BN 128
#define BK 16
__global__ __launch_bounds__(256, 2) void k_stage2(
    const float* __restrict__ wo, const float* __restrict__ bo,
    float* __restrict__ out) {
    int e = blockIdx.z;
    int cnt = g_count[e];
    int rowbase = blockIdx.x * BM;
    if (rowbase >= cnt) return;
    int colbase = blockIdx.y * BN;

    __shared__ unsigned As[2][BK][BM + 4];   // As[k][m], tf32 bits
    __shared__ unsigned Bs[2][BK][BN + 4];   // Bs[k][n], tf32 bits

    int tid = threadIdx.x;
    int warp = tid >> 5, lane = tid & 31;
    int wm = warp >> 1, wn = warp & 1;       // 4 x 2 warp grid

    float C[2][8][4];
#pragma unroll
    for (int mi = 0; mi < 2; mi++)
#pragma unroll
        for (int ni = 0; ni < 8; ni++)
#pragma unroll
            for (int q = 0; q < 4; q++) C[mi][ni][q] = 0.0f;

    const float* mide = g_mid + (size_t)e * NB * NH;
    const float* woe  = wo + (size_t)e * NH * NH;

    // staging indices
    int a_r  = tid >> 2, a_kq = tid & 3;     // rows a_r, a_r+64; k-quad a_kq
    int b_c4 = tid & 31, b_kk = tid >> 5;    // k rows b_kk, b_kk+8
    int gr0 = rowbase + a_r, gr1 = gr0 + 64;

    float4 pa[2], pb[2];
    pa[0] = (gr0 < cnt) ? *(const float4*)(mide + (size_t)gr0 * NH + a_kq * 4)
                        : make_float4(0.f, 0.f, 0.f, 0.f);
    pa[1] = (gr1 < cnt) ? *(const float4*)(mide + (size_t)gr1 * NH + a_kq * 4)
                        : make_float4(0.f, 0.f, 0.f, 0.f);
    pb[0] = *(const float4*)(woe + (size_t)b_kk * NH + colbase + b_c4 * 4);
    pb[1] = *(const float4*)(woe + (size_t)(b_kk + 8) * NH + colbase + b_c4 * 4);
#pragma unroll
    for (int q = 0; q < 2; q++) {
        int r = (q == 0) ? a_r : a_r + 64;
        As[0][a_kq * 4 + 0][r] = f2tf32(q == 0 ? pa[0].x : pa[1].x);
        As[0][a_kq * 4 + 1][r] = f2tf32(q == 0 ? pa[0].y : pa[1].y);
        As[0][a_kq * 4 + 2][r] = f2tf32(q == 0 ? pa[0].z : pa[1].z);
        As[0][a_kq * 4 + 3][r] = f2tf32(q == 0 ? pa[0].w : pa[1].w);
        int kk = (q == 0) ? b_kk : b_kk + 8;
        Bs[0][kk][b_c4 * 4 + 0] = f2tf32(q == 0 ? pb[0].x : pb[1].x);
        Bs[0][kk][b_c4 * 4 + 1] = f2tf32(q == 0 ? pb[0].y : pb[1].y);
        Bs[0][kk][b_c4 * 4 + 2] = f2tf32(q == 0 ? pb[0].z : pb[1].z);
        Bs[0][kk][b_c4 * 4 + 3] = f2tf32(q == 0 ? pb[0].w : pb[1].w);
    }
    __syncthreads();

    int arow = lane >> 2, acol = lane & 3;
    int brow = lane & 3,  bcol = lane >> 2;

#pragma unroll 1
    for (int t = 0; t < NH / BK; t++) {
        int p = t & 1;
        int k1 = (t + 1) * BK;
        bool hasnext = k1 < NH;
        if (hasnext) {
            pa[0] = (gr0 < cnt) ? *(const float4*)(mide + (size_t)gr0 * NH + k1 + a_kq * 4)
                                : make_float4(0.f, 0.f, 0.f, 0.f);
            pa[1] = (gr1 < cnt) ? *(const float4*)(mide + (size_t)gr1 * NH + k1 + a_kq * 4)
                                : make_float4(0.f, 0.f, 0.f, 0.f);
            pb[0] = *(const float4*)(woe + (size_t)(k1 + b_kk) * NH + colbase + b_c4 * 4);
            pb[1] = *(const float4*)(woe + (size_t)(k1 + b_kk + 8) * NH + colbase + b_c4 * 4);
        }

#pragma unroll
        for (int kc = 0; kc < BK; kc += 8) {
            unsigned afr[2][4];
#pragma unroll
            for (int mi = 0; mi < 2; mi++) {
                int m = wm * 32 + mi * 16 + arow;
                afr[mi][0] = As[p][kc + acol][m];
                afr[mi][1] = As[p][kc + acol][m + 8];
                afr[mi][2] = As[p][kc + acol + 4][m];
                afr[mi][3] = As[p][kc + acol + 4][m + 8];
            }
            unsigned bfr[8][2];
#pragma unroll
            for (int ni = 0; ni < 8; ni++) {
                int n = wn * 64 + ni * 8 + bcol;
                bfr[ni][0] = Bs[p][kc + brow][n];
                bfr[ni][1] = Bs[p][kc + brow + 4][n];
            }
#pragma unroll
            for (int mi = 0; mi < 2; mi++)
#pragma unroll
                for (int ni = 0; ni < 8; ni++)
                    mma_tf32(C[mi][ni], afr[mi], bfr[ni]);
        }

        if (hasnext) {
            int u = 1 - p;
#pragma unroll
            for (int q = 0; q < 2; q++) {
                int r = (q == 0) ? a_r : a_r + 64;
                As[u][a_kq * 4 + 0][r] = f2tf32(q == 0 ? pa[0].x : pa[1].x);
                As[u][a_kq * 4 + 1][r] = f2tf32(q == 0 ? pa[0].y : pa[1].y);
                As[u][a_kq * 4 + 2][r] = f2tf32(q == 0 ? pa[0].z : pa[1].z);
                As[u][a_kq * 4 + 3][r] = f2tf32(q == 0 ? pa[0].w : pa[1].w);
                int kk = (q == 0) ? b_kk : b_kk + 8;
                Bs[u][kk][b_c4 * 4 + 0] = f2tf32(q == 0 ? pb[0].x : pb[1].x);
                Bs[u][kk][b_c4 * 4 + 1] = f2tf32(q == 0 ? pb[0].y : pb[1].y);
                Bs[u][kk][b_c4 * 4 + 2] = f2tf32(q == 0 ? pb[0].z : pb[1].z);
                Bs[u][kk][b_c4 * 4 + 3] = f2tf32(q == 0 ? pb[0].w : pb[1].w);
            }
            __syncthreads();
        }
    }

    // epilogue: out[b] += gate * (C + bo)
    const float* boe = bo + (size_t)e * NH + colbase;
    int crow = lane >> 2, ccol = (lane & 3) * 2;
#pragma unroll
    for (int mi = 0; mi < 2; mi++) {
#pragma unroll
        for (int half = 0; half < 2; half++) {
            int r = wm * 32 + mi * 16 + crow + half * 8;
            int s = rowbase + r;
            if (s < cnt) {
                int b = g_rows[e * NB + s];
                float g = g_gate[e * NB + s];
                float* o = out + (size_t)b * NH + colbase;
#pragma unroll
                for (int ni = 0; ni < 8; ni++) {
                    int col = wn * 64 + ni * 8 + ccol;
                    float2 bo2 = __ldg((const float2*)(boe + col));
                    atomicAdd(o + col,     g * (C[mi][ni][half * 2 + 0] + bo2.x));
                    atomicAdd(o + col + 1, g * (C[mi][ni][half * 2 + 1] + bo2.y));
                }
            }
        }
    }
}

// ---------------- launch ----------------
extern "C" void kernel_launch(void* const* d_in, const int* in_sizes, int n_in,
                              void* d_out, int out_size) {
    const float* gate_input   = (const float*)d_in[0];
    const float* expert_input = (const float*)d_in[1];
    const int*   task_bh      = (const int*)  d_in[2];
    const float* gate_w       = (const float*)d_in[3];
    const float* gate_b       = (const float*)d_in[4];
    const float* freqs        = (const float*)d_in[5];
    const float* w1           = (const float*)d_in[6];
    const float* b1           = (const float*)d_in[7];
    const float* ln_g         = (const float*)d_in[8];
    const float* ln_b         = (const float*)d_in[9];
    const float* wo           = (const float*)d_in[10];
    const float* bo           = (const float*)d_in[11];
    float* out = (float*)d_out;

    k_init<<<1024, 256>>>(out, out_size);
    k_gate<<<NB / 256, 256>>>(gate_input, task_bh, gate_w, gate_b);
    k_stage1<<<dim3(NB / 16, NE), 256>>>(expert_input, freqs, w1, b1, ln_g, ln_b);
    k_stage2<<<dim3(NB / BM, NH / BN, NE), 256>>>(wo, bo, out);
}